// round 1
// baseline (speedup 1.0000x reference)
#include <cuda_runtime.h>
#include <cstdint>

// ChessboardLayer: (B,H,W,C)=(32,256,256,32) fp32 space-to-depth into 8x8 cells.
// out[b][r][c][(i*ww + j)*C + ch] = in[b][r*32+i][c*32+j][ch],  hh=ww=32, C=32.
//
// For fixed (b,r,i,c), the (j,ch) span is 1024 contiguous floats (4 KiB) in
// BOTH input and output:
//   in  chunk id = ((b*8+r)*32 + i)*8 + c
//   out chunk id = ((b*8+r)*8 + c)*32 + i
// => pure 4KiB-block transpose. One 256-thread CTA copies one chunk with
// float4, fully coalesced both sides.

__global__ void __launch_bounds__(256, 8)
chessboard_kernel(const float4* __restrict__ in, float4* __restrict__ out) {
    // blockIdx.x = input chunk id, 65536 total
    unsigned blk = blockIdx.x;
    unsigned c   = blk & 7u;          // col-band 0..7
    unsigned i   = (blk >> 3) & 31u;  // row within band 0..31
    unsigned br  = blk >> 8;          // (b*8 + r), 0..255

    unsigned out_chunk = br * 256u + c * 32u + i;

    // 1024 floats per chunk = 256 float4
    unsigned t = threadIdx.x;
    out[(size_t)out_chunk * 256u + t] = in[(size_t)blk * 256u + t];
}

extern "C" void kernel_launch(void* const* d_in, const int* in_sizes, int n_in,
                              void* d_out, int out_size) {
    const float4* in  = (const float4*)d_in[0];
    float4*       out = (float4*)d_out;
    // total chunks = 32 (B) * 8 (r) * 32 (i) * 8 (c) = 65536
    chessboard_kernel<<<65536, 256>>>(in, out);
}

// round 2
// speedup vs baseline: 1.0027x; 1.0027x over previous
#include <cuda_runtime.h>
#include <cstdint>

// ChessboardLayer: (B,H,W,C)=(32,256,256,32) fp32 space-to-depth into 8x8 cells.
// Pure 4KiB-block transpose:
//   in  chunk id q = ((b*8+r)*32 + i)*8 + c
//   out chunk id   = ((b*8+r)*8 + c)*32 + i
//
// R2: 4 chunks per CTA (consecutive input ids -> 16KiB contiguous read),
// batched loads (MLP=4) + streaming cache hints. Grid 16384 x 256.

__global__ void __launch_bounds__(256, 8)
chessboard_kernel(const float4* __restrict__ in, float4* __restrict__ out) {
    unsigned base = blockIdx.x * 4u;     // first input chunk id of this CTA
    unsigned t    = threadIdx.x;

    // Batched loads: 4 independent LDG.128 (16KiB contiguous region)
    float4 v0 = __ldcs(&in[(size_t)(base + 0u) * 256u + t]);
    float4 v1 = __ldcs(&in[(size_t)(base + 1u) * 256u + t]);
    float4 v2 = __ldcs(&in[(size_t)(base + 2u) * 256u + t]);
    float4 v3 = __ldcs(&in[(size_t)(base + 3u) * 256u + t]);

    // Output chunk id for input chunk q: c=q&7, i=(q>>3)&31, br=q>>8
    //   out = br*256 + c*32 + i
    #pragma unroll
    for (int k = 0; k < 4; k++) {
        unsigned q  = base + (unsigned)k;
        unsigned oc = (q >> 8) * 256u + (q & 7u) * 32u + ((q >> 3) & 31u);
        float4 v = (k == 0) ? v0 : (k == 1) ? v1 : (k == 2) ? v2 : v3;
        __stcs(&out[(size_t)oc * 256u + t], v);
    }
}

extern "C" void kernel_launch(void* const* d_in, const int* in_sizes, int n_in,
                              void* d_out, int out_size) {
    const float4* in  = (const float4*)d_in[0];
    float4*       out = (float4*)d_out;
    // 65536 chunks total / 4 per CTA = 16384 CTAs
    chessboard_kernel<<<16384, 256>>>(in, out);
}

// round 3
// speedup vs baseline: 1.0035x; 1.0008x over previous
#include <cuda_runtime.h>
#include <cstdint>

// ChessboardLayer: (B,H,W,C)=(32,256,256,32) fp32 space-to-depth into 8x8 cells.
// Pure 4KiB-block transpose:
//   in  chunk id q = ((b*8+r)*32 + i)*8 + c
//   out chunk id   = ((b*8+r)*8 + c)*32 + i
//
// R2: 4 chunks per CTA (consecutive input ids -> 16KiB contiguous read),
// batched loads (MLP=4) + streaming cache hints. Grid 16384 x 256.

__global__ void __launch_bounds__(256, 8)
chessboard_kernel(const float4* __restrict__ in, float4* __restrict__ out) {
    unsigned base = blockIdx.x * 4u;     // first input chunk id of this CTA
    unsigned t    = threadIdx.x;

    // Batched loads: 4 independent LDG.128 (16KiB contiguous region)
    float4 v0 = __ldcs(&in[(size_t)(base + 0u) * 256u + t]);
    float4 v1 = __ldcs(&in[(size_t)(base + 1u) * 256u + t]);
    float4 v2 = __ldcs(&in[(size_t)(base + 2u) * 256u + t]);
    float4 v3 = __ldcs(&in[(size_t)(base + 3u) * 256u + t]);

    // Output chunk id for input chunk q: c=q&7, i=(q>>3)&31, br=q>>8
    //   out = br*256 + c*32 + i
    #pragma unroll
    for (int k = 0; k < 4; k++) {
        unsigned q  = base + (unsigned)k;
        unsigned oc = (q >> 8) * 256u + (q & 7u) * 32u + ((q >> 3) & 31u);
        float4 v = (k == 0) ? v0 : (k == 1) ? v1 : (k == 2) ? v2 : v3;
        __stcs(&out[(size_t)oc * 256u + t], v);
    }
}

extern "C" void kernel_launch(void* const* d_in, const int* in_sizes, int n_in,
                              void* d_out, int out_size) {
    const float4* in  = (const float4*)d_in[0];
    float4*       out = (float4*)d_out;
    // 65536 chunks total / 4 per CTA = 16384 CTAs
    chessboard_kernel<<<16384, 256>>>(in, out);
}